// round 13
// baseline (speedup 1.0000x reference)
#include <cuda_runtime.h>
#include <cuda_bf16.h>
#include <cstdint>
#include <float.h>

// Problem constants (RaggedTopKGatingModule: N=524288, E=64, K=8)
#define E_EXPERTS 64
#define TOPK 8
#define BLOCK_A 256
#define TOK_PER_BLOCK 64                               // 4 lanes per token
#define SLOTS_PER_CHUNK (TOK_PER_BLOCK * TOPK)         // 512
#define MAX_SLOTS (524288 * 8)
#define MAX_CHUNKS 8192
#define ROW_B 320                                      // 4 quarters of 80B
#define QTR_B 80                                       // 64B data + 16B pad

// Scratch (no allocation allowed; __device__ globals)
// packed per-slot: (expert_id << 8) | within_chunk_rank   (rank < 64)
__device__ uint16_t g_pack[MAX_SLOTS];                 // 8 MB
__device__ int      g_chunk_hist[MAX_CHUNKS * E_EXPERTS];
__device__ int      g_chunk_base[MAX_CHUNKS * E_EXPERTS];

// ---------------------------------------------------------------------------
// Kernel A: quad-split exact top-8 (16 elems/lane + 2-stage smem merge)
//           + softmax + logits copy + warp-local ordered ranking
// ---------------------------------------------------------------------------
__global__ __launch_bounds__(BLOCK_A, 6)
void topk_rank_kernel(const float* __restrict__ logits,
                      float* __restrict__ out_scores,
                      float* __restrict__ out_assign,
                      float* __restrict__ out_logits,
                      int n_tokens)
{
    __shared__ uint8_t  sh_stage[TOK_PER_BLOCK * ROW_B];   // 20 KB
    __shared__ uint64_t sh_e64[TOK_PER_BLOCK];             // 512 B

    // phase-2-only tables overlaid into sh_stage (dead after phase-1)
    int* sh_cnt  = (int*)sh_stage;                  // 8*64 ints = 2 KB
    int* sh_base = (int*)(sh_stage + 2048);         // 8*64 ints = 2 KB

    const int tid  = threadIdx.x;
    const int lane = tid & 31;
    const int warp = tid >> 5;
    const int chunk = blockIdx.x;
    const int tok_base = chunk * TOK_PER_BLOCK;

    // -------- Phase 0: coalesced copy + padded smem staging --------
    {
        const size_t gbase = (size_t)tok_base * E_EXPERTS;
        const float4* src = (const float4*)(logits + gbase);
        float4*       dst = (float4*)(out_logits + gbase);
        #pragma unroll
        for (int k = 0; k < 4; ++k) {
            const int i = tid + k * BLOCK_A;           // 0..1023 float4
            float4 v = src[i];
            dst[i] = v;
            const int tok = i >> 4, rem = i & 15;
            const int soff = tok * ROW_B + (rem >> 2) * QTR_B + (rem & 3) * 16;
            *(float4*)(sh_stage + soff) = v;
        }
    }
    __syncthreads();

    // -------- Phase 1: quad-split exact top-8 + softmax --------
    {
        const int lt = tid >> 2;            // local token 0..63
        const int q  = tid & 3;             // quarter: experts [16q,16q+16)
        const int t  = tok_base + lt;
        uint8_t* myq = sh_stage + lt * ROW_B + q * QTR_B;

        float tv[TOPK];
        int   ti[TOPK];
        #pragma unroll
        for (int k = 0; k < TOPK; ++k) { tv[k] = -FLT_MAX; ti[k] = 0; }

        float s0 = 0.f, s1 = 0.f, s2 = 0.f, s3 = 0.f;

        #pragma unroll
        for (int j = 0; j < 4; ++j) {       // 16 experts per lane, from smem
            float4 qv = *(const float4*)(myq + j * 16);
            float xs[4] = {qv.x, qv.y, qv.z, qv.w};
            s0 += __expf(qv.x); s1 += __expf(qv.y);
            s2 += __expf(qv.z); s3 += __expf(qv.w);
            #pragma unroll
            for (int u = 0; u < 4; ++u) {
                const int le = j * 4 + u;   // local expert id 0..15
                const float x = xs[u];
                // strict >: lowest-index-first on exact ties within quarter
                if (x > tv[TOPK - 1]) {
                    tv[TOPK - 1] = x; ti[TOPK - 1] = le;
                    #pragma unroll
                    for (int jj = TOPK - 1; jj > 0; --jj) {
                        if (tv[jj] > tv[jj - 1]) {
                            float tf = tv[jj]; tv[jj] = tv[jj - 1]; tv[jj - 1] = tf;
                            int   tt = ti[jj]; ti[jj] = ti[jj - 1]; ti[jj - 1] = tt;
                        }
                    }
                }
            }
        }

        // publish own sorted list IN PLACE (region already consumed)
        *(float4*)(myq +  0) = make_float4(tv[0], tv[1], tv[2], tv[3]);
        *(float4*)(myq + 16) = make_float4(tv[4], tv[5], tv[6], tv[7]);
        uint64_t idp = 0;
        #pragma unroll
        for (int k = 0; k < TOPK; ++k)
            idp |= (uint64_t)(uint8_t)(q * 16 + ti[k]) << (8 * k);
        *(uint64_t*)(myq + 32) = idp;

        // softmax total across the 4 lanes of this token
        float mysum = (s0 + s1) + (s2 + s3);
        float tot = mysum + __shfl_xor_sync(0xffffffffu, mysum, 1);
        tot = tot + __shfl_xor_sync(0xffffffffu, tot, 2);
        __syncwarp();                       // all quad publishes visible

        // stage 1: q0 merges (q0,q1); q2 merges (q2,q3)   [same code path]
        if ((q & 1) == 0) {
            const float*   KA = (const float*)myq;
            const float*   KB = (const float*)(myq + QTR_B);
            const uint8_t* EA = myq + 32;
            const uint8_t* EB = myq + QTR_B + 32;
            uint64_t mip = 0;
            int i = 0, j = 0;
            #pragma unroll
            for (int k = 0; k < TOPK; ++k) {
                float ka = (i < 8) ? KA[i] : -FLT_MAX;
                float kb = (j < 8) ? KB[j] : -FLT_MAX;
                const bool takeA = (ka >= kb);   // ties -> lower experts
                const float   kk = takeA ? ka : kb;
                const uint8_t ee = takeA ? EA[i] : EB[j];
                i += takeA; j += !takeA;
                *(float*)(myq + 48 + 4 * k) = kk;    // merged keys 48..80
                mip |= (uint64_t)ee << (8 * k);
            }
            *(uint64_t*)(myq + 80) = mip;   // ids into next (dead) quarter
        }
        __syncwarp();

        // stage 2: q0 merges merged01 with merged23 -> final top-8
        if (q == 0) {
            const float*   KA = (const float*)(myq + 48);
            const float*   KB = (const float*)(myq + 2 * QTR_B + 48);
            const uint8_t* EA = myq + 80;
            const uint8_t* EB = myq + 2 * QTR_B + 80;
            const float inv = 1.0f / tot;

            float sc[TOPK];
            uint64_t ep = 0;
            int i = 0, j = 0;
            #pragma unroll
            for (int k = 0; k < TOPK; ++k) {
                float ka = (i < 8) ? KA[i] : -FLT_MAX;
                float kb = (j < 8) ? KB[j] : -FLT_MAX;
                const bool takeA = (ka >= kb);   // ties -> lower experts
                const float   kk = takeA ? ka : kb;
                const uint8_t ee = takeA ? EA[i] : EB[j];
                i += takeA; j += !takeA;
                sc[k] = __expf(kk) * inv;
                ep |= (uint64_t)ee << (8 * k);
            }
            sh_e64[lt] = ep;
            float4* srow = (float4*)(out_scores + (size_t)t * TOPK);
            srow[0] = make_float4(sc[0], sc[1], sc[2], sc[3]);
            srow[1] = make_float4(sc[4], sc[5], sc[6], sc[7]);
        }
    }
    __syncthreads();                        // stage region now dead

    // zero overlaid warp counters
    sh_cnt[tid] = 0; sh_cnt[tid + BLOCK_A] = 0;
    __syncthreads();

    // -------- Phase 2: warp-local ordered multisplit (64 slots per warp) ----
    const uint8_t* eb = (const uint8_t*)sh_e64;
    const unsigned lanemask_lt = (1u << lane) - 1u;
    int mye[2], myr[2];
    #pragma unroll
    for (int r = 0; r < 2; ++r) {
        const int slot = warp * 64 + r * 32 + lane;    // token-major order
        const int e = eb[slot];
        unsigned mask = __match_any_sync(0xffffffffu, e);
        const int lrank  = __popc(mask & lanemask_lt);
        const int leader = __ffs(mask) - 1;
        int prev = 0;
        if (lane == leader) {               // leader-only RMW: program-ordered
            prev = sh_cnt[warp * E_EXPERTS + e];
            sh_cnt[warp * E_EXPERTS + e] = prev + __popc(mask);
        }
        prev = __shfl_sync(0xffffffffu, prev, leader);
        mye[r] = e; myr[r] = prev + lrank;
        __syncwarp();                       // order leader STS before next round
    }
    __syncthreads();

    // single cross-warp scan
    if (tid < E_EXPERTS) {
        int run = 0;
        #pragma unroll
        for (int w = 0; w < 8; ++w) {
            sh_base[w * E_EXPERTS + tid] = run;
            run += sh_cnt[w * E_EXPERTS + tid];
        }
        g_chunk_hist[chunk * E_EXPERTS + tid] = run;
    }
    __syncthreads();

    const size_t slot_base = (size_t)chunk * SLOTS_PER_CHUNK;
    #pragma unroll
    for (int r = 0; r < 2; ++r) {
        const int s = warp * 64 + r * 32 + lane;
        const int rank = sh_base[warp * E_EXPERTS + mye[r]] + myr[r];  // < 64
        g_pack[slot_base + s] = (uint16_t)((mye[r] << 8) | rank);
        out_assign[slot_base + s] = (float)mye[r];     // coalesced 128B/warp
    }
}

// ---------------------------------------------------------------------------
// Kernel B: per-expert exclusive scan over 8192 chunk histograms (8 per thread)
// ---------------------------------------------------------------------------
__global__ void scan_kernel(float* __restrict__ out_counts, int n_chunks)
{
    __shared__ int s[1024];
    const int e = blockIdx.x;
    const int c = threadIdx.x;

    int v[8];
    int tot = 0;
    #pragma unroll
    for (int i = 0; i < 8; ++i) {
        const int ci = 8 * c + i;
        v[i] = (ci < n_chunks) ? g_chunk_hist[ci * E_EXPERTS + e] : 0;
        tot += v[i];
    }
    s[c] = tot;
    __syncthreads();

    #pragma unroll
    for (int off = 1; off < 1024; off <<= 1) {
        int t = (c >= off) ? s[c - off] : 0;
        __syncthreads();
        s[c] += t;
        __syncthreads();
    }
    const int incl = s[c];
    int run = incl - tot;
    #pragma unroll
    for (int i = 0; i < 8; ++i) {
        const int ci = 8 * c + i;
        if (ci < n_chunks) g_chunk_base[ci * E_EXPERTS + e] = run;
        run += v[i];
    }
    if (c == 1023) out_counts[e] = (float)incl;
}

// ---------------------------------------------------------------------------
// Kernel C: final offsets only   (4 slots / thread)
// ---------------------------------------------------------------------------
__global__ __launch_bounds__(256, 8)
void offsets_kernel(float* __restrict__ out_offs, int n_quads)
{
    const int q = blockIdx.x * blockDim.x + threadIdx.x;
    if (q >= n_quads) return;
    const int idx = q * 4;
    const int chunk = idx >> 9;                     // / SLOTS_PER_CHUNK (512)

    ushort4 p4 = *(const ushort4*)(g_pack + idx);
    const int* __restrict__ base = g_chunk_base + chunk * E_EXPERTS;

    float4 o;
    o.x = (float)(base[p4.x >> 8] + (p4.x & 255));
    o.y = (float)(base[p4.y >> 8] + (p4.y & 255));
    o.z = (float)(base[p4.z >> 8] + (p4.z & 255));
    o.w = (float)(base[p4.w >> 8] + (p4.w & 255));
    *(float4*)(out_offs + idx) = o;
}

// ---------------------------------------------------------------------------
extern "C" void kernel_launch(void* const* d_in, const int* in_sizes, int n_in,
                              void* d_out, int out_size)
{
    // inputs: [0]=expert_counts(E), [1]=assignments(N*K), [2]=offsets(N*K), [3]=logits(N*E)
    const float* logits = (const float*)d_in[3];
    const int n_tokens = in_sizes[3] / E_EXPERTS;       // 524288
    const int n_slots  = n_tokens * TOPK;               // 4194304
    const int n_chunks = n_tokens / TOK_PER_BLOCK;      // 8192

    float* out = (float*)d_out;
    // layout: counts[E] | scores[N*K] | assign[N*K] | offs[N*K] | logits[N*E]
    float* out_counts = out;
    float* out_scores = out + E_EXPERTS;
    float* out_assign = out_scores + (size_t)n_slots;
    float* out_offs   = out_assign + (size_t)n_slots;
    float* out_logits = out_offs   + (size_t)n_slots;

    topk_rank_kernel<<<n_chunks, BLOCK_A>>>(logits, out_scores, out_assign,
                                            out_logits, n_tokens);
    scan_kernel<<<E_EXPERTS, 1024>>>(out_counts, n_chunks);
    const int n_quads = n_slots / 4;
    offsets_kernel<<<(n_quads + 255) / 256, 256>>>(out_offs, n_quads);
}

// round 14
// speedup vs baseline: 1.1162x; 1.1162x over previous
#include <cuda_runtime.h>
#include <cuda_bf16.h>
#include <cstdint>
#include <float.h>

// Problem constants (RaggedTopKGatingModule: N=524288, E=64, K=8)
#define E_EXPERTS 64
#define TOPK 8
#define BLOCK_A 256
#define TOK_PER_BLOCK 128                              // 2 lanes per token
#define SLOTS_PER_CHUNK (TOK_PER_BLOCK * TOPK)         // 1024
#define MAX_SLOTS (524288 * 8)
#define MAX_CHUNKS 4096
#define ROW_B 288                                      // 256B row + 2x16B pad
#define HALF_B 144

// Scratch (no allocation allowed; __device__ globals)
// packed per-slot: (expert_id << 8) | within_chunk_rank   (rank <= 127)
__device__ uint16_t g_pack[MAX_SLOTS];                 // 8 MB
__device__ int      g_chunk_hist[MAX_CHUNKS * E_EXPERTS];
__device__ int      g_chunk_base[MAX_CHUNKS * E_EXPERTS];

// ---------------------------------------------------------------------------
// Kernel A: staged-smem pair-split top-8 (float/fma-pipe sort) + softmax
//           + logits copy + warp-local ordered ranking + assign stores
// ---------------------------------------------------------------------------
__global__ __launch_bounds__(BLOCK_A, 6)
void topk_rank_kernel(const float* __restrict__ logits,
                      float* __restrict__ out_scores,
                      float* __restrict__ out_assign,
                      float* __restrict__ out_logits,
                      int n_tokens)
{
    __shared__ uint8_t  sh_stage[TOK_PER_BLOCK * ROW_B];   // 36 KB
    __shared__ uint64_t sh_e64[TOK_PER_BLOCK];             // 1 KB

    // phase-2-only tables overlaid into sh_stage (dead after phase-1 merge)
    int* sh_cnt  = (int*)sh_stage;                  // 8*64 ints = 2 KB
    int* sh_base = (int*)(sh_stage + 2048);         // 8*64 ints = 2 KB

    const int tid  = threadIdx.x;
    const int lane = tid & 31;
    const int warp = tid >> 5;
    const int chunk = blockIdx.x;
    const int tok_base = chunk * TOK_PER_BLOCK;

    // -------- Phase 0: coalesced copy + padded smem staging --------
    {
        const size_t gbase = (size_t)tok_base * E_EXPERTS;
        const float4* src = (const float4*)(logits + gbase);
        float4*       dst = (float4*)(out_logits + gbase);
        #pragma unroll
        for (int k = 0; k < 8; ++k) {
            const int i = tid + k * BLOCK_A;           // 0..2047 float4
            float4 v = src[i];
            dst[i] = v;
            const int tok = i >> 4, rem = i & 15;
            const int soff = tok * ROW_B + (rem >> 3) * HALF_B + (rem & 7) * 16;
            *(float4*)(sh_stage + soff) = v;
        }
    }
    __syncthreads();

    // -------- Phase 1: pair-split exact top-8 + softmax --------
    {
        const int lt   = tid >> 1;          // local token 0..127
        const int half = tid & 1;           // 0: experts 0-31, 1: 32-63
        const int t = tok_base + lt;
        uint8_t* myhalf = sh_stage + lt * ROW_B + half * HALF_B;

        float tv[TOPK];
        int   ti[TOPK];
        #pragma unroll
        for (int k = 0; k < TOPK; ++k) { tv[k] = -FLT_MAX; ti[k] = 0; }

        float s0 = 0.f, s1 = 0.f, s2 = 0.f, s3 = 0.f;

        #pragma unroll
        for (int j = 0; j < 8; ++j) {       // 32 experts per lane, from smem
            float4 q = *(const float4*)(myhalf + j * 16);
            float xs[4] = {q.x, q.y, q.z, q.w};
            s0 += __expf(q.x); s1 += __expf(q.y);
            s2 += __expf(q.z); s3 += __expf(q.w);
            #pragma unroll
            for (int u = 0; u < 4; ++u) {
                const int le = j * 4 + u;   // local expert id
                const float x = xs[u];
                // strict >: lowest-index-first on exact ties within half
                if (x > tv[TOPK - 1]) {
                    tv[TOPK - 1] = x; ti[TOPK - 1] = le;
                    #pragma unroll
                    for (int jj = TOPK - 1; jj > 0; --jj) {
                        if (tv[jj] > tv[jj - 1]) {
                            float tf = tv[jj]; tv[jj] = tv[jj - 1]; tv[jj - 1] = tf;
                            int   tt = ti[jj]; ti[jj] = ti[jj - 1]; ti[jj - 1] = tt;
                        }
                    }
                }
            }
        }

        // publish local top-8 IN PLACE into own (already consumed) region
        *(float4*)(myhalf +  0) = make_float4(tv[0], tv[1], tv[2], tv[3]);
        *(float4*)(myhalf + 16) = make_float4(tv[4], tv[5], tv[6], tv[7]);
        uint64_t idp = 0;
        #pragma unroll
        for (int k = 0; k < TOPK; ++k)
            idp |= (uint64_t)(uint8_t)(half * 32 + ti[k]) << (8 * k);
        *(uint64_t*)(myhalf + 32) = idp;

        const float mysum = (s0 + s1) + (s2 + s3);
        const float total = mysum + __shfl_xor_sync(0xffffffffu, mysum, 1);
        __syncwarp();                       // pair's STS visible

        if (!half) {
            const float*   KA = (const float*)(sh_stage + lt * ROW_B);
            const float*   KB = (const float*)(sh_stage + lt * ROW_B + HALF_B);
            const uint8_t* EA = sh_stage + lt * ROW_B + 32;
            const uint8_t* EB = sh_stage + lt * ROW_B + HALF_B + 32;
            const float inv = 1.0f / total;

            float sc[TOPK];
            uint64_t ep = 0;
            int i = 0, j = 0;
            #pragma unroll
            for (int k = 0; k < TOPK; ++k) {
                float ka = (i < 8) ? KA[i] : -FLT_MAX;
                float kb = (j < 8) ? KB[j] : -FLT_MAX;
                // ties -> even half (experts 0-31) = lower index first
                const bool takeA = (ka >= kb);
                const float   kk = takeA ? ka : kb;
                const uint8_t ee = takeA ? EA[i] : EB[j];
                i += takeA; j += !takeA;
                sc[k] = __expf(kk) * inv;
                ep |= (uint64_t)ee << (8 * k);
            }
            sh_e64[lt] = ep;
            float4* srow = (float4*)(out_scores + (size_t)t * TOPK);
            srow[0] = make_float4(sc[0], sc[1], sc[2], sc[3]);
            srow[1] = make_float4(sc[4], sc[5], sc[6], sc[7]);
        }
    }
    __syncthreads();                        // merge reads of stage complete

    // zero overlaid warp counters (stage region now dead)
    sh_cnt[tid] = 0; sh_cnt[tid + BLOCK_A] = 0;
    __syncthreads();

    // -------- Phase 2: warp-local ordered multisplit (slots 128w..128w+127) --
    const uint8_t* eb = (const uint8_t*)sh_e64;
    const unsigned lanemask_lt = (1u << lane) - 1u;
    int mye[4], myr[4];
    #pragma unroll
    for (int q = 0; q < 4; ++q) {
        const int slot = warp * 128 + q * 32 + lane;   // token-major order
        const int e = eb[slot];
        unsigned mask = __match_any_sync(0xffffffffu, e);
        const int lrank  = __popc(mask & lanemask_lt);
        const int leader = __ffs(mask) - 1;
        int prev = 0;
        if (lane == leader) {               // leader-only RMW: program-ordered
            prev = sh_cnt[warp * E_EXPERTS + e];
            sh_cnt[warp * E_EXPERTS + e] = prev + __popc(mask);
        }
        prev = __shfl_sync(0xffffffffu, prev, leader);
        mye[q] = e; myr[q] = prev + lrank;
        __syncwarp();                       // order leader STS before next round
    }
    __syncthreads();

    // single cross-warp scan
    if (tid < E_EXPERTS) {
        int run = 0;
        #pragma unroll
        for (int w = 0; w < 8; ++w) {
            sh_base[w * E_EXPERTS + tid] = run;
            run += sh_cnt[w * E_EXPERTS + tid];
        }
        g_chunk_hist[chunk * E_EXPERTS + tid] = run;
    }
    __syncthreads();

    const size_t slot_base = (size_t)chunk * SLOTS_PER_CHUNK;
    #pragma unroll
    for (int q = 0; q < 4; ++q) {
        const int s = warp * 128 + q * 32 + lane;
        const int rank = sh_base[warp * E_EXPERTS + mye[q]] + myr[q];  // <=127
        g_pack[slot_base + s] = (uint16_t)((mye[q] << 8) | rank);
        out_assign[slot_base + s] = (float)mye[q];     // coalesced 128B/warp
    }
}

// ---------------------------------------------------------------------------
// Kernel B: per-expert exclusive scan over 4096 chunk histograms
//           shfl-based: 2 block barriers total (was 20)
// ---------------------------------------------------------------------------
__global__ void scan_kernel(float* __restrict__ out_counts, int n_chunks)
{
    __shared__ int warp_base[32];
    const int e    = blockIdx.x;
    const int c    = threadIdx.x;           // 0..1023
    const int lane = c & 31;
    const int w    = c >> 5;

    int v[4];
    #pragma unroll
    for (int i = 0; i < 4; ++i) {
        const int ci = 4 * c + i;
        v[i] = (ci < n_chunks) ? g_chunk_hist[ci * E_EXPERTS + e] : 0;
    }
    const int quad = v[0] + v[1] + v[2] + v[3];

    // inclusive warp scan of quad
    int incl = quad;
    #pragma unroll
    for (int off = 1; off < 32; off <<= 1) {
        int t = __shfl_up_sync(0xffffffffu, incl, off);
        if (lane >= off) incl += t;
    }
    if (lane == 31) warp_base[w] = incl;
    __syncthreads();

    if (w == 0) {
        int s = warp_base[lane];            // 32 warp totals
        int si = s;
        #pragma unroll
        for (int off = 1; off < 32; off <<= 1) {
            int t = __shfl_up_sync(0xffffffffu, si, off);
            if (lane >= off) si += t;
        }
        warp_base[lane] = si - s;           // exclusive warp base
        if (lane == 31) out_counts[e] = (float)si;   // grand total
    }
    __syncthreads();

    int run = warp_base[w] + incl - quad;   // exclusive thread base
    #pragma unroll
    for (int i = 0; i < 4; ++i) {
        const int ci = 4 * c + i;
        if (ci < n_chunks) g_chunk_base[ci * E_EXPERTS + e] = run;
        run += v[i];
    }
}

// ---------------------------------------------------------------------------
// Kernel C: final offsets only   (4 slots / thread)
// ---------------------------------------------------------------------------
__global__ __launch_bounds__(256, 8)
void offsets_kernel(float* __restrict__ out_offs, int n_quads)
{
    const int q = blockIdx.x * blockDim.x + threadIdx.x;
    if (q >= n_quads) return;
    const int idx = q * 4;
    const int chunk = idx >> 10;                    // / SLOTS_PER_CHUNK (1024)

    ushort4 p4 = *(const ushort4*)(g_pack + idx);
    const int* __restrict__ base = g_chunk_base + chunk * E_EXPERTS;

    float4 o;
    o.x = (float)(base[p4.x >> 8] + (p4.x & 255));
    o.y = (float)(base[p4.y >> 8] + (p4.y & 255));
    o.z = (float)(base[p4.z >> 8] + (p4.z & 255));
    o.w = (float)(base[p4.w >> 8] + (p4.w & 255));
    *(float4*)(out_offs + idx) = o;
}

// ---------------------------------------------------------------------------
extern "C" void kernel_launch(void* const* d_in, const int* in_sizes, int n_in,
                              void* d_out, int out_size)
{
    // inputs: [0]=expert_counts(E), [1]=assignments(N*K), [2]=offsets(N*K), [3]=logits(N*E)
    const float* logits = (const float*)d_in[3];
    const int n_tokens = in_sizes[3] / E_EXPERTS;       // 524288
    const int n_slots  = n_tokens * TOPK;               // 4194304
    const int n_chunks = n_tokens / TOK_PER_BLOCK;      // 4096

    float* out = (float*)d_out;
    // layout: counts[E] | scores[N*K] | assign[N*K] | offs[N*K] | logits[N*E]
    float* out_counts = out;
    float* out_scores = out + E_EXPERTS;
    float* out_assign = out_scores + (size_t)n_slots;
    float* out_offs   = out_assign + (size_t)n_slots;
    float* out_logits = out_offs   + (size_t)n_slots;

    topk_rank_kernel<<<n_chunks, BLOCK_A>>>(logits, out_scores, out_assign,
                                            out_logits, n_tokens);
    scan_kernel<<<E_EXPERTS, 1024>>>(out_counts, n_chunks);
    const int n_quads = n_slots / 4;
    offsets_kernel<<<(n_quads + 255) / 256, 256>>>(out_offs, n_quads);
}

// round 15
// speedup vs baseline: 1.1184x; 1.0020x over previous
#include <cuda_runtime.h>
#include <cuda_bf16.h>
#include <cstdint>
#include <float.h>

// Problem constants (RaggedTopKGatingModule: N=524288, E=64, K=8)
#define E_EXPERTS 64
#define TOPK 8
#define BLOCK_A 256
#define TOK_PER_BLOCK 128                              // 2 lanes per token
#define SLOTS_PER_CHUNK (TOK_PER_BLOCK * TOPK)         // 1024
#define MAX_SLOTS (524288 * 8)
#define MAX_CHUNKS 4096
#define ROW_B 288                                      // 256B row + 2x16B pad
#define HALF_B 144

// Scratch (no allocation allowed; __device__ globals)
// packed per-slot: (expert_id << 8) | within_chunk_rank   (rank <= 127)
__device__ uint16_t g_pack[MAX_SLOTS];                 // 8 MB
__device__ int      g_chunk_hist[MAX_CHUNKS * E_EXPERTS];
__device__ int      g_chunk_base[MAX_CHUNKS * E_EXPERTS];

// 256-bit global load/store (sm_100+, PTX 8.7)
#define LDG256(p, r0,r1,r2,r3,r4,r5,r6,r7) \
    asm volatile("ld.global.nc.v8.f32 {%0,%1,%2,%3,%4,%5,%6,%7}, [%8];" \
        : "=f"(r0),"=f"(r1),"=f"(r2),"=f"(r3), \
          "=f"(r4),"=f"(r5),"=f"(r6),"=f"(r7) : "l"(p))

#define STG256(p, r0,r1,r2,r3,r4,r5,r6,r7) \
    asm volatile("st.global.v8.f32 [%0], {%1,%2,%3,%4,%5,%6,%7,%8};" \
        :: "l"(p), "f"(r0),"f"(r1),"f"(r2),"f"(r3), \
           "f"(r4),"f"(r5),"f"(r6),"f"(r7) : "memory")

// ---------------------------------------------------------------------------
// Kernel A: staged-smem pair-split top-8 (float/fma-pipe sort) + softmax
//           + logits copy (256-bit) + warp-local ordered ranking + assigns
// ---------------------------------------------------------------------------
__global__ __launch_bounds__(BLOCK_A, 6)
void topk_rank_kernel(const float* __restrict__ logits,
                      float* __restrict__ out_scores,
                      float* __restrict__ out_assign,
                      float* __restrict__ out_logits,
                      int n_tokens)
{
    __shared__ uint8_t  sh_stage[TOK_PER_BLOCK * ROW_B];   // 36 KB
    __shared__ uint64_t sh_e64[TOK_PER_BLOCK];             // 1 KB

    // phase-2-only tables overlaid into sh_stage (dead after phase-1 merge)
    int* sh_cnt  = (int*)sh_stage;                  // 8*64 ints = 2 KB
    int* sh_base = (int*)(sh_stage + 2048);         // 8*64 ints = 2 KB

    const int tid  = threadIdx.x;
    const int lane = tid & 31;
    const int warp = tid >> 5;
    const int chunk = blockIdx.x;
    const int tok_base = chunk * TOK_PER_BLOCK;

    // -------- Phase 0: 256-bit coalesced copy + padded smem staging --------
    {
        const size_t gbase = (size_t)tok_base * E_EXPERTS;
        const float* srcf = logits + gbase;
        float*       dstf = out_logits + gbase;
        #pragma unroll
        for (int k = 0; k < 4; ++k) {
            const int i8 = tid + k * BLOCK_A;          // 32B-unit index 0..1023
            float r0,r1,r2,r3,r4,r5,r6,r7;
            LDG256(srcf + (size_t)i8 * 8, r0,r1,r2,r3,r4,r5,r6,r7);
            STG256(dstf + (size_t)i8 * 8, r0,r1,r2,r3,r4,r5,r6,r7);
            const int tok = i8 >> 3, rem = i8 & 7;
            uint8_t* s = sh_stage + tok * ROW_B + (rem >> 2) * HALF_B
                                  + (rem & 3) * 32;
            *(float4*)(s)      = make_float4(r0, r1, r2, r3);
            *(float4*)(s + 16) = make_float4(r4, r5, r6, r7);
        }
    }
    __syncthreads();

    // -------- Phase 1: pair-split exact top-8 + softmax --------
    {
        const int lt   = tid >> 1;          // local token 0..127
        const int half = tid & 1;           // 0: experts 0-31, 1: 32-63
        const int t = tok_base + lt;
        uint8_t* myhalf = sh_stage + lt * ROW_B + half * HALF_B;

        float tv[TOPK];
        int   ti[TOPK];
        #pragma unroll
        for (int k = 0; k < TOPK; ++k) { tv[k] = -FLT_MAX; ti[k] = 0; }

        float s0 = 0.f, s1 = 0.f, s2 = 0.f, s3 = 0.f;

        #pragma unroll
        for (int j = 0; j < 8; ++j) {       // 32 experts per lane, from smem
            float4 q = *(const float4*)(myhalf + j * 16);
            float xs[4] = {q.x, q.y, q.z, q.w};
            s0 += __expf(q.x); s1 += __expf(q.y);
            s2 += __expf(q.z); s3 += __expf(q.w);
            #pragma unroll
            for (int u = 0; u < 4; ++u) {
                const int le = j * 4 + u;   // local expert id
                const float x = xs[u];
                // strict >: lowest-index-first on exact ties within half
                if (x > tv[TOPK - 1]) {
                    tv[TOPK - 1] = x; ti[TOPK - 1] = le;
                    #pragma unroll
                    for (int jj = TOPK - 1; jj > 0; --jj) {
                        if (tv[jj] > tv[jj - 1]) {
                            float tf = tv[jj]; tv[jj] = tv[jj - 1]; tv[jj - 1] = tf;
                            int   tt = ti[jj]; ti[jj] = ti[jj - 1]; ti[jj - 1] = tt;
                        }
                    }
                }
            }
        }

        // publish local top-8 IN PLACE into own (already consumed) region
        *(float4*)(myhalf +  0) = make_float4(tv[0], tv[1], tv[2], tv[3]);
        *(float4*)(myhalf + 16) = make_float4(tv[4], tv[5], tv[6], tv[7]);
        uint64_t idp = 0;
        #pragma unroll
        for (int k = 0; k < TOPK; ++k)
            idp |= (uint64_t)(uint8_t)(half * 32 + ti[k]) << (8 * k);
        *(uint64_t*)(myhalf + 32) = idp;

        const float mysum = (s0 + s1) + (s2 + s3);
        const float total = mysum + __shfl_xor_sync(0xffffffffu, mysum, 1);
        __syncwarp();                       // pair's STS visible

        if (!half) {
            const float*   KA = (const float*)(sh_stage + lt * ROW_B);
            const float*   KB = (const float*)(sh_stage + lt * ROW_B + HALF_B);
            const uint8_t* EA = sh_stage + lt * ROW_B + 32;
            const uint8_t* EB = sh_stage + lt * ROW_B + HALF_B + 32;
            const float inv = 1.0f / total;

            float sc[TOPK];
            uint64_t ep = 0;
            int i = 0, j = 0;
            #pragma unroll
            for (int k = 0; k < TOPK; ++k) {
                float ka = (i < 8) ? KA[i] : -FLT_MAX;
                float kb = (j < 8) ? KB[j] : -FLT_MAX;
                // ties -> even half (experts 0-31) = lower index first
                const bool takeA = (ka >= kb);
                const float   kk = takeA ? ka : kb;
                const uint8_t ee = takeA ? EA[i] : EB[j];
                i += takeA; j += !takeA;
                sc[k] = __expf(kk) * inv;
                ep |= (uint64_t)ee << (8 * k);
            }
            sh_e64[lt] = ep;
            STG256(out_scores + (size_t)t * TOPK,
                   sc[0], sc[1], sc[2], sc[3], sc[4], sc[5], sc[6], sc[7]);
        }
    }
    __syncthreads();                        // merge reads of stage complete

    // zero overlaid warp counters (stage region now dead)
    sh_cnt[tid] = 0; sh_cnt[tid + BLOCK_A] = 0;
    __syncthreads();

    // -------- Phase 2: warp-local ordered multisplit (slots 128w..128w+127) --
    const uint8_t* eb = (const uint8_t*)sh_e64;
    const unsigned lanemask_lt = (1u << lane) - 1u;
    int mye[4], myr[4];
    #pragma unroll
    for (int q = 0; q < 4; ++q) {
        const int slot = warp * 128 + q * 32 + lane;   // token-major order
        const int e = eb[slot];
        unsigned mask = __match_any_sync(0xffffffffu, e);
        const int lrank  = __popc(mask & lanemask_lt);
        const int leader = __ffs(mask) - 1;
        int prev = 0;
        if (lane == leader) {               // leader-only RMW: program-ordered
            prev = sh_cnt[warp * E_EXPERTS + e];
            sh_cnt[warp * E_EXPERTS + e] = prev + __popc(mask);
        }
        prev = __shfl_sync(0xffffffffu, prev, leader);
        mye[q] = e; myr[q] = prev + lrank;
        __syncwarp();                       // order leader STS before next round
    }
    __syncthreads();

    // single cross-warp scan
    if (tid < E_EXPERTS) {
        int run = 0;
        #pragma unroll
        for (int w = 0; w < 8; ++w) {
            sh_base[w * E_EXPERTS + tid] = run;
            run += sh_cnt[w * E_EXPERTS + tid];
        }
        g_chunk_hist[chunk * E_EXPERTS + tid] = run;
    }
    __syncthreads();

    const size_t slot_base = (size_t)chunk * SLOTS_PER_CHUNK;
    #pragma unroll
    for (int q = 0; q < 4; ++q) {
        const int s = warp * 128 + q * 32 + lane;
        const int rank = sh_base[warp * E_EXPERTS + mye[q]] + myr[q];  // <=127
        g_pack[slot_base + s] = (uint16_t)((mye[q] << 8) | rank);
        out_assign[slot_base + s] = (float)mye[q];     // coalesced 128B/warp
    }
}

// ---------------------------------------------------------------------------
// Kernel B: per-expert exclusive scan over 4096 chunk histograms
//           shfl-based: 2 block barriers total
// ---------------------------------------------------------------------------
__global__ void scan_kernel(float* __restrict__ out_counts, int n_chunks)
{
    __shared__ int warp_base[32];
    const int e    = blockIdx.x;
    const int c    = threadIdx.x;           // 0..1023
    const int lane = c & 31;
    const int w    = c >> 5;

    int v[4];
    #pragma unroll
    for (int i = 0; i < 4; ++i) {
        const int ci = 4 * c + i;
        v[i] = (ci < n_chunks) ? g_chunk_hist[ci * E_EXPERTS + e] : 0;
    }
    const int quad = v[0] + v[1] + v[2] + v[3];

    // inclusive warp scan of quad
    int incl = quad;
    #pragma unroll
    for (int off = 1; off < 32; off <<= 1) {
        int t = __shfl_up_sync(0xffffffffu, incl, off);
        if (lane >= off) incl += t;
    }
    if (lane == 31) warp_base[w] = incl;
    __syncthreads();

    if (w == 0) {
        int s = warp_base[lane];            // 32 warp totals
        int si = s;
        #pragma unroll
        for (int off = 1; off < 32; off <<= 1) {
            int t = __shfl_up_sync(0xffffffffu, si, off);
            if (lane >= off) si += t;
        }
        warp_base[lane] = si - s;           // exclusive warp base
        if (lane == 31) out_counts[e] = (float)si;   // grand total
    }
    __syncthreads();

    int run = warp_base[w] + incl - quad;   // exclusive thread base
    #pragma unroll
    for (int i = 0; i < 4; ++i) {
        const int ci = 4 * c + i;
        if (ci < n_chunks) g_chunk_base[ci * E_EXPERTS + e] = run;
        run += v[i];
    }
}

// ---------------------------------------------------------------------------
// Kernel C: final offsets only   (4 slots / thread)
// ---------------------------------------------------------------------------
__global__ __launch_bounds__(256, 8)
void offsets_kernel(float* __restrict__ out_offs, int n_quads)
{
    const int q = blockIdx.x * blockDim.x + threadIdx.x;
    if (q >= n_quads) return;
    const int idx = q * 4;
    const int chunk = idx >> 10;                    // / SLOTS_PER_CHUNK (1024)

    ushort4 p4 = *(const ushort4*)(g_pack + idx);
    const int* __restrict__ base = g_chunk_base + chunk * E_EXPERTS;

    float4 o;
    o.x = (float)(base[p4.x >> 8] + (p4.x & 255));
    o.y = (float)(base[p4.y >> 8] + (p4.y & 255));
    o.z = (float)(base[p4.z >> 8] + (p4.z & 255));
    o.w = (float)(base[p4.w >> 8] + (p4.w & 255));
    *(float4*)(out_offs + idx) = o;
}

// ---------------------------------------------------------------------------
extern "C" void kernel_launch(void* const* d_in, const int* in_sizes, int n_in,
                              void* d_out, int out_size)
{
    // inputs: [0]=expert_counts(E), [1]=assignments(N*K), [2]=offsets(N*K), [3]=logits(N*E)
    const float* logits = (const float*)d_in[3];
    const int n_tokens = in_sizes[3] / E_EXPERTS;       // 524288
    const int n_slots  = n_tokens * TOPK;               // 4194304
    const int n_chunks = n_tokens / TOK_PER_BLOCK;      // 4096

    float* out = (float*)d_out;
    // layout: counts[E] | scores[N*K] | assign[N*K] | offs[N*K] | logits[N*E]
    float* out_counts = out;
    float* out_scores = out + E_EXPERTS;
    float* out_assign = out_scores + (size_t)n_slots;
    float* out_offs   = out_assign + (size_t)n_slots;
    float* out_logits = out_offs   + (size_t)n_slots;

    topk_rank_kernel<<<n_chunks, BLOCK_A>>>(logits, out_scores, out_assign,
                                            out_logits, n_tokens);
    scan_kernel<<<E_EXPERTS, 1024>>>(out_counts, n_chunks);
    const int n_quads = n_slots / 4;
    offsets_kernel<<<(n_quads + 255) / 256, 256>>>(out_offs, n_quads);
}